// round 3
// baseline (speedup 1.0000x reference)
#include <cuda_runtime.h>
#include <cstdint>

// Problem: BS=32, SEQ_LEN=4096, HIDDEN=1024
//  prefix[b]  = row-sum of contiguous-1s attention_mask row
//  n_valid[b] = max(prefix-1, 1)
//  u[b][e]    = jax.random.uniform(key(42), (32,1024))
//               JAX with jax_threefry_partitionable=True (modern default):
//               bits[i] = xor(threefry2x32((0,42), (hi64(i)=0, lo64(i)=i)))
//  idx        = min(int(u * n_valid), n_valid-1)
//  out[b][e]  = tokens[b][idx][e]

#define BS 32
#define SEQ_LEN 4096
#define HIDDEN 1024

__device__ __forceinline__ uint32_t rotl32(uint32_t x, int r) {
    return (x << r) | (x >> (32 - r));
}

// Threefry-2x32, 20 rounds, matching jax._src.prng.threefry2x32
__device__ __forceinline__ void threefry2x32(uint32_t k0, uint32_t k1,
                                             uint32_t& x0, uint32_t& x1) {
    uint32_t ks0 = k0, ks1 = k1, ks2 = k0 ^ k1 ^ 0x1BD11BDAu;
    x0 += ks0;
    x1 += ks1;
    // group 0: rot [13,15,26,6], inject ks1, ks2+1
    x0 += x1; x1 = rotl32(x1, 13); x1 ^= x0;
    x0 += x1; x1 = rotl32(x1, 15); x1 ^= x0;
    x0 += x1; x1 = rotl32(x1, 26); x1 ^= x0;
    x0 += x1; x1 = rotl32(x1,  6); x1 ^= x0;
    x0 += ks1; x1 += ks2 + 1u;
    // group 1: rot [17,29,16,24], inject ks2, ks0+2
    x0 += x1; x1 = rotl32(x1, 17); x1 ^= x0;
    x0 += x1; x1 = rotl32(x1, 29); x1 ^= x0;
    x0 += x1; x1 = rotl32(x1, 16); x1 ^= x0;
    x0 += x1; x1 = rotl32(x1, 24); x1 ^= x0;
    x0 += ks2; x1 += ks0 + 2u;
    // group 2: rot [13,15,26,6], inject ks0, ks1+3
    x0 += x1; x1 = rotl32(x1, 13); x1 ^= x0;
    x0 += x1; x1 = rotl32(x1, 15); x1 ^= x0;
    x0 += x1; x1 = rotl32(x1, 26); x1 ^= x0;
    x0 += x1; x1 = rotl32(x1,  6); x1 ^= x0;
    x0 += ks0; x1 += ks1 + 3u;
    // group 3: rot [17,29,16,24], inject ks1, ks2+4
    x0 += x1; x1 = rotl32(x1, 17); x1 ^= x0;
    x0 += x1; x1 = rotl32(x1, 29); x1 ^= x0;
    x0 += x1; x1 = rotl32(x1, 16); x1 ^= x0;
    x0 += x1; x1 = rotl32(x1, 24); x1 ^= x0;
    x0 += ks1; x1 += ks2 + 4u;
    // group 4: rot [13,15,26,6], inject ks2, ks0+5
    x0 += x1; x1 = rotl32(x1, 13); x1 ^= x0;
    x0 += x1; x1 = rotl32(x1, 15); x1 ^= x0;
    x0 += x1; x1 = rotl32(x1, 26); x1 ^= x0;
    x0 += x1; x1 = rotl32(x1,  6); x1 ^= x0;
    x0 += ks2; x1 += ks0 + 5u;
}

__global__ __launch_bounds__(1024, 1)
void condensed_embracement_kernel(const float* __restrict__ tokens,
                                  const int* __restrict__ mask,
                                  float* __restrict__ out) {
    const int b = blockIdx.x;    // batch
    const int e = threadIdx.x;   // embedding index, 0..1023

    __shared__ int warp_sums[32];
    __shared__ int s_nvalid;

    // --- mask row-sum: 4096 int32 per batch, 1024 threads x int4 ---
    const int4* mrow = reinterpret_cast<const int4*>(mask + b * SEQ_LEN);
    int4 m = mrow[e];
    int partial = m.x + m.y + m.z + m.w;

    #pragma unroll
    for (int off = 16; off > 0; off >>= 1)
        partial += __shfl_down_sync(0xFFFFFFFFu, partial, off);
    int lane = e & 31;
    int wid  = e >> 5;
    if (lane == 0) warp_sums[wid] = partial;
    __syncthreads();
    if (wid == 0) {
        int s = warp_sums[lane];  // exactly 32 warps
        #pragma unroll
        for (int off = 16; off > 0; off >>= 1)
            s += __shfl_down_sync(0xFFFFFFFFu, s, off);
        if (lane == 0) {
            int prefix = s;       // contiguous-1s => sum == where(all1, seq_len, argmin)
            int nv = prefix - 1;
            s_nvalid = nv > 1 ? nv : 1;
        }
    }
    __syncthreads();
    const int nv = s_nvalid;

    // --- Threefry, partitionable mode: per-element 64-bit counter ---
    // counts_hi = i >> 32 = 0, counts_lo = i; bits = x0_out ^ x1_out
    const int i = b * HIDDEN + e;               // flattened (b,e), < 2^32
    uint32_t x0 = 0u, x1 = (uint32_t)i;
    threefry2x32(0u, 42u, x0, x1);
    const uint32_t bits = x0 ^ x1;

    // uniform [0,1): bitcast((bits>>9)|0x3f800000) - 1
    const float u = __uint_as_float((bits >> 9) | 0x3F800000u) - 1.0f;

    // idx = min(trunc(u * nv), nv-1); bare fp32 mul, C-trunc == astype(int32)
    int idx = (int)(__fmul_rn(u, (float)nv));
    const int idx_max = nv - 1;
    if (idx > idx_max) idx = idx_max;

    // --- gather ---
    const size_t src = (size_t)b * (SEQ_LEN * HIDDEN) + (size_t)idx * HIDDEN + (size_t)e;
    out[i] = __ldg(tokens + src);
}

extern "C" void kernel_launch(void* const* d_in, const int* in_sizes, int n_in,
                              void* d_out, int out_size) {
    // Bind inputs by SIZE (robust to metadata ordering).
    const float* tokens = nullptr;
    const int*   mask   = nullptr;
    for (int k = 0; k < n_in; k++) {
        if (in_sizes[k] == BS * SEQ_LEN * HIDDEN) tokens = (const float*)d_in[k];
        else if (in_sizes[k] == BS * SEQ_LEN)     mask   = (const int*)d_in[k];
    }
    float* out = (float*)d_out;
    condensed_embracement_kernel<<<BS, 1024>>>(tokens, mask, out);
}

// round 7
// speedup vs baseline: 1.0047x; 1.0047x over previous
#include <cuda_runtime.h>
#include <cstdint>

// Problem: BS=32, SEQ_LEN=4096, HIDDEN=1024
//  prefix[b]  = row-sum of contiguous-1s attention_mask row
//  n_valid[b] = max(prefix-1, 1)
//  u[b][e]    = jax.random.uniform(key(42), (32,1024)), partitionable threefry:
//               bits[i] = xor(threefry2x32((0,42), (0, i)))
//  idx        = min(int(u * n_valid), n_valid-1)
//  out[b][e]  = tokens[b][idx][e]
//
// Layout: 128 CTAs x 256 threads. CTA (b, part) covers embedding cols
// [part*256, part*256+256). Each CTA redundantly reduces the full mask row
// (16KB; first reader pulls DRAM, the other 3 hit L2) so no cross-CTA sync
// is needed, while the scattered gather spreads over ~128 SMs instead of 32.

#define BS 32
#define SEQ_LEN 4096
#define HIDDEN 1024
#define PARTS 4                  // CTAs per batch
#define THREADS 256              // HIDDEN / PARTS

__device__ __forceinline__ uint32_t rotl32(uint32_t x, int r) {
    return (x << r) | (x >> (32 - r));
}

// Threefry-2x32, 20 rounds, matching jax._src.prng.threefry2x32
__device__ __forceinline__ void threefry2x32(uint32_t k0, uint32_t k1,
                                             uint32_t& x0, uint32_t& x1) {
    uint32_t ks0 = k0, ks1 = k1, ks2 = k0 ^ k1 ^ 0x1BD11BDAu;
    x0 += ks0;
    x1 += ks1;
    x0 += x1; x1 = rotl32(x1, 13); x1 ^= x0;
    x0 += x1; x1 = rotl32(x1, 15); x1 ^= x0;
    x0 += x1; x1 = rotl32(x1, 26); x1 ^= x0;
    x0 += x1; x1 = rotl32(x1,  6); x1 ^= x0;
    x0 += ks1; x1 += ks2 + 1u;
    x0 += x1; x1 = rotl32(x1, 17); x1 ^= x0;
    x0 += x1; x1 = rotl32(x1, 29); x1 ^= x0;
    x0 += x1; x1 = rotl32(x1, 16); x1 ^= x0;
    x0 += x1; x1 = rotl32(x1, 24); x1 ^= x0;
    x0 += ks2; x1 += ks0 + 2u;
    x0 += x1; x1 = rotl32(x1, 13); x1 ^= x0;
    x0 += x1; x1 = rotl32(x1, 15); x1 ^= x0;
    x0 += x1; x1 = rotl32(x1, 26); x1 ^= x0;
    x0 += x1; x1 = rotl32(x1,  6); x1 ^= x0;
    x0 += ks0; x1 += ks1 + 3u;
    x0 += x1; x1 = rotl32(x1, 17); x1 ^= x0;
    x0 += x1; x1 = rotl32(x1, 29); x1 ^= x0;
    x0 += x1; x1 = rotl32(x1, 16); x1 ^= x0;
    x0 += x1; x1 = rotl32(x1, 24); x1 ^= x0;
    x0 += ks1; x1 += ks2 + 4u;
    x0 += x1; x1 = rotl32(x1, 13); x1 ^= x0;
    x0 += x1; x1 = rotl32(x1, 15); x1 ^= x0;
    x0 += x1; x1 = rotl32(x1, 26); x1 ^= x0;
    x0 += x1; x1 = rotl32(x1,  6); x1 ^= x0;
    x0 += ks2; x1 += ks0 + 5u;
}

__global__ __launch_bounds__(THREADS, 1)
void condensed_embracement_kernel(const float* __restrict__ tokens,
                                  const int* __restrict__ mask,
                                  float* __restrict__ out) {
    const int b    = blockIdx.x >> 2;        // batch
    const int part = blockIdx.x & (PARTS - 1);
    const int tid  = threadIdx.x;
    const int col  = part * THREADS + tid;   // embedding index 0..1023

    __shared__ int warp_sums[THREADS / 32];
    __shared__ int s_nvalid;

    // --- start threefry early (pure ALU, independent of mask load) ---
    const int i = b * HIDDEN + col;          // flattened (b, col)
    uint32_t x0 = 0u, x1 = (uint32_t)i;
    threefry2x32(0u, 42u, x0, x1);
    const uint32_t bits = x0 ^ x1;
    const float u = __uint_as_float((bits >> 9) | 0x3F800000u) - 1.0f;

    // --- full mask row sum (redundant per CTA): 4096 ints, 256 threads x 4 int4 ---
    const int4* mrow = reinterpret_cast<const int4*>(mask + b * SEQ_LEN);
    int partial = 0;
    #pragma unroll
    for (int k = 0; k < 4; k++) {
        int4 m = mrow[tid + k * THREADS];    // coalesced, MLP=4
        partial += m.x + m.y + m.z + m.w;
    }

    #pragma unroll
    for (int off = 16; off > 0; off >>= 1)
        partial += __shfl_down_sync(0xFFFFFFFFu, partial, off);
    const int lane = tid & 31;
    const int wid  = tid >> 5;
    if (lane == 0) warp_sums[wid] = partial;
    __syncthreads();
    if (wid == 0) {
        int s = (lane < THREADS / 32) ? warp_sums[lane] : 0;
        #pragma unroll
        for (int off = 4; off > 0; off >>= 1)
            s += __shfl_down_sync(0xFFFFFFFFu, s, off);
        if (lane == 0) {
            int nv = s - 1;                  // prefix - 1
            s_nvalid = nv > 1 ? nv : 1;
        }
    }
    __syncthreads();
    const int nv = s_nvalid;

    // idx = min(trunc(u * nv), nv-1); bare fp32 mul, C-trunc == astype(int32)
    int idx = (int)(__fmul_rn(u, (float)nv));
    const int idx_max = nv - 1;
    if (idx > idx_max) idx = idx_max;

    // --- gather ---
    const size_t src = (size_t)b * (SEQ_LEN * HIDDEN) + (size_t)idx * HIDDEN + (size_t)col;
    out[i] = __ldg(tokens + src);
}

extern "C" void kernel_launch(void* const* d_in, const int* in_sizes, int n_in,
                              void* d_out, int out_size) {
    // Bind inputs by SIZE (robust to metadata ordering).
    const float* tokens = nullptr;
    const int*   mask   = nullptr;
    for (int k = 0; k < n_in; k++) {
        if (in_sizes[k] == BS * SEQ_LEN * HIDDEN) tokens = (const float*)d_in[k];
        else if (in_sizes[k] == BS * SEQ_LEN)     mask   = (const int*)d_in[k];
    }
    float* out = (float*)d_out;
    condensed_embracement_kernel<<<BS * PARTS, THREADS>>>(tokens, mask, out);
}